// round 9
// baseline (speedup 1.0000x reference)
#include <cuda_runtime.h>
#include <cstdint>

// Tensor-train chain, fp32 f32x2, TB=28/grid=147, balanced {4,4,3,3} pair
// split rotated over l-quarters. R9: v stored pre-duplicated in smem so the
// k-loop consumes C as natural float2 pairs -> ZERO dup-movs in the hot loop.
// Single __syncthreads per step; distributed finalize via float4 scratch.

#define BATCH   4096
#define LEN     128
#define RANK    64
#define NSTEP   126
#define CSTEP   16384          // floats per mid-core step
#define TB      28             // batches per CTA (14 pairs)
#define NPAIR   14
#define GRID    147            // 147*28 = 4116 >= 4096
#define THREADS 512
#define VPU     66             // ulonglong2 per vbuf pair-row (64 + 2 pad)

// smem: Cbuf 2*CSTEP floats | vbuf [14][VPU] ull2 | scr [2][4][14][32] float4
#define SCR_F4  (2*4*NPAIR*32)
#define SMEM_BYTES (2*CSTEP*4 + NPAIR*VPU*16 + SCR_F4*16)

extern __shared__ float smem_f[];

__device__ __forceinline__ uint64_t fma2(uint64_t a, uint64_t b, uint64_t c) {
    uint64_t d;
    asm("fma.rn.f32x2 %0, %1, %2, %3;" : "=l"(d) : "l"(a), "l"(b), "l"(c));
    return d;
}
__device__ __forceinline__ uint64_t mul2(uint64_t a, uint64_t b) {
    uint64_t d;
    asm("mul.rn.f32x2 %0, %1, %2;" : "=l"(d) : "l"(a), "l"(b));
    return d;
}
__device__ __forceinline__ uint64_t dup2(float f) {
    uint64_t d;
    asm("mov.b64 %0, {%1, %1};" : "=l"(d) : "f"(f));
    return d;
}
__device__ __forceinline__ float2 u2f(uint64_t a) {
    return *reinterpret_cast<float2*>(&a);
}
__device__ __forceinline__ uint32_t smem_u32(const void* p) {
    return (uint32_t)__cvta_generic_to_shared(p);
}
__device__ __forceinline__ void cp_async16(uint32_t dst, const void* src) {
    asm volatile("cp.async.cg.shared.global [%0], [%1], 16;\n" :: "r"(dst), "l"(src));
}

// One step's heavy work for a warp owning P pairs.
// CsU: uint64 view of current C quarter, pre-offset by lane (r-pair {2lane,2lane+1}).
// vb:  vbuf base for this warp's first pair (ull2*, rows [p*VPU + l]).
// scrW: float4 scratch write base for (parity, q, base), indexed [p*32 + lane].
template<int P>
__device__ __forceinline__ void step_body(
    int s, const uint64_t* __restrict__ CsU, const ulonglong2* __restrict__ vb,
    const float* __restrict__ x, const int* xo0, const int* xo1,
    float4* __restrict__ scrW, int lane)
{
    uint64_t t[4][P][2];     // [i][pair][batch] f32x2 over {r0,r1}
    #pragma unroll
    for (int i = 0; i < 4; ++i)
        #pragma unroll
        for (int p = 0; p < P; ++p) { t[i][p][0] = 0ull; t[i][p][1] = 0ull; }

    #pragma unroll
    for (int l = 0; l < 16; ++l) {
        uint64_t vA[P], vB[P];
        #pragma unroll
        for (int p = 0; p < P; ++p) {
            ulonglong2 V = vb[p * VPU + l];   // {va,va},{vb,vb} broadcast LDS.128
            vA[p] = V.x;
            vB[p] = V.y;
        }
        #pragma unroll
        for (int i = 0; i < 4; ++i) {
            uint64_t c2 = CsU[(4 * l + i) * 32];   // {C[k][2lane], C[k][2lane+1]}
            #pragma unroll
            for (int p = 0; p < P; ++p) {
                t[i][p][0] = fma2(vA[p], c2, t[i][p][0]);
                t[i][p][1] = fma2(vB[p], c2, t[i][p][1]);
            }
        }
    }

    // combine with x[., s+1, .] and write q-partials (r-packed per batch)
    #pragma unroll
    for (int p = 0; p < P; ++p) {
        float4 xa = *(const float4*)(x + xo0[p] + (s + 1) * 4);
        float4 xb = *(const float4*)(x + xo1[p] + (s + 1) * 4);
        uint64_t nA = mul2(dup2(xa.x), t[0][p][0]);
        nA = fma2(dup2(xa.y), t[1][p][0], nA);
        nA = fma2(dup2(xa.z), t[2][p][0], nA);
        nA = fma2(dup2(xa.w), t[3][p][0], nA);
        uint64_t nB = mul2(dup2(xb.x), t[0][p][1]);
        nB = fma2(dup2(xb.y), t[1][p][1], nB);
        nB = fma2(dup2(xb.z), t[2][p][1], nB);
        nB = fma2(dup2(xb.w), t[3][p][1], nB);
        float2 fa = u2f(nA);    // {vn_a[r0], vn_a[r1]}
        float2 fb = u2f(nB);    // {vn_b[r0], vn_b[r1]}
        scrW[p * 32 + lane] = make_float4(fa.x, fb.x, fa.y, fb.y);
    }
}

__global__ void __launch_bounds__(THREADS, 1)
tt_chain_kernel(const float* __restrict__ x,    // [B, 128, 4]
                const float* __restrict__ fc,   // [4, 64]
                const float* __restrict__ mc,   // [126, 64, 4, 64]
                const float* __restrict__ lc,   // [64, 4]
                float* __restrict__ out)        // [B, 1]
{
    float*      Cbuf = smem_f;
    ulonglong2* vbuf = (ulonglong2*)(smem_f + 2*CSTEP);   // [14][VPU]
    float4*     scr  = (float4*)(vbuf + NPAIR*VPU);       // [2][4][14][32]
    float2*     scrf = (float2*)scr;  // f2 view: [(par*4+q)*NPAIR+pb]*64 + r
    float2*     epi  = (float2*)scr;  // epilogue partials, parity-0 region

    const int tid  = threadIdx.x;
    const int warp = tid >> 5;
    const int lane = tid & 31;
    const int q    = warp >> 2;            // l-quarter [16q, 16q+16)
    const int sg   = warp & 3;             // -> SMSP
    const int Pw   = (((q + sg) & 3) < 2) ? 4 : 3;
    int base = 0;
    #pragma unroll
    for (int t = 0; t < 3; ++t)
        if (t < sg) base += (((q + t) & 3) < 2) ? 4 : 3;

    // clamped x offsets for this warp's pairs
    int xo0[4], xo1[4];
    #pragma unroll
    for (int p = 0; p < 4; ++p) {
        int pb = base + p;
        int b0 = blockIdx.x * TB + 2 * pb;
        int b1 = b0 + 1;
        if (b0 > BATCH - 1) b0 = BATCH - 1;
        if (b1 > BATCH - 1) b1 = BATCH - 1;
        xo0[p] = b0 * (LEN * 4);
        xo1[p] = b1 * (LEN * 4);
    }

    // ---- prefetch C[0] ----
    {
        uint32_t dst = smem_u32(Cbuf);
        #pragma unroll
        for (int j = 0; j < 8; ++j) {
            int idx = j * THREADS + tid;
            cp_async16(dst + idx * 16, mc + idx * 4);
        }
        asm volatile("cp.async.commit_group;\n");
    }

    // ---- prologue: fill this warp's vbuf slots with duplicated v0 ----
    #pragma unroll
    for (int v = 0; v < 2; ++v) {
        int slot = lane + 32 * v;
        int pi = slot >> 4;
        int ro = slot & 15;
        if (pi < Pw) {
            int l = 16 * q + ro;
            float4 xA = *(const float4*)(x + xo0[pi]);
            float4 xB = *(const float4*)(x + xo1[pi]);
            float f0 = fc[l], f1 = fc[64 + l], f2 = fc[128 + l], f3 = fc[192 + l];
            float va = f0*xA.x + f1*xA.y + f2*xA.z + f3*xA.w;
            float vv = f0*xB.x + f1*xB.y + f2*xB.z + f3*xB.w;
            ulonglong2 w; w.x = dup2(va); w.y = dup2(vv);
            vbuf[(base + pi) * VPU + l] = w;
        }
    }
    asm volatile("cp.async.wait_group 0;\n");   // own C[0] chunks landed

    // ---- main chain: ONE __syncthreads per step ----
    #pragma unroll 1
    for (int s = 0; s < NSTEP; ++s) {
        __syncthreads();   // all C[s] copies landed; scr[(s-1)&1] complete; Cbuf[(s+1)&1] free

        if (s + 1 < NSTEP) {
            uint32_t dst = smem_u32(Cbuf + ((s + 1) & 1) * CSTEP);
            const float* src = mc + (size_t)(s + 1) * CSTEP;
            #pragma unroll
            for (int j = 0; j < 8; ++j) {
                int idx = j * THREADS + tid;
                cp_async16(dst + idx * 16, src + idx * 4);
            }
            asm volatile("cp.async.commit_group;\n");
        }

        // finalize v_s into vbuf (this warp's own slots, duplicated), except s==0
        if (s > 0) {
            const int par = (s - 1) & 1;
            #pragma unroll
            for (int v = 0; v < 2; ++v) {
                int slot = lane + 32 * v;
                int pi = slot >> 4;
                int ro = slot & 15;
                if (pi < Pw) {
                    int pb = base + pi;
                    int l  = 16 * q + ro;
                    const float2* sp = scrf + (size_t)((par * 4) * NPAIR + pb) * 64 + l;
                    float2 a = sp[0];
                    float2 b = sp[NPAIR * 64];
                    float2 c = sp[2 * NPAIR * 64];
                    float2 d = sp[3 * NPAIR * 64];
                    float va = (a.x + b.x) + (c.x + d.x);
                    float vv = (a.y + b.y) + (c.y + d.y);
                    ulonglong2 w; w.x = dup2(va); w.y = dup2(vv);
                    vbuf[pb * VPU + l] = w;
                }
            }
        }
        __syncwarp();

        const uint64_t* CsU = (const uint64_t*)(Cbuf + (s & 1) * CSTEP)
                            + (size_t)(64 * q) * 32 + lane;
        const ulonglong2* vb = vbuf + base * VPU + 16 * q;
        float4* scrW = scr + (size_t)(((s & 1) * 4 + q) * NPAIR + base) * 32;

        if (Pw == 4) step_body<4>(s, CsU, vb, x, xo0, xo1, scrW, lane);
        else         step_body<3>(s, CsU, vb, x, xo0, xo1, scrW, lane);

        asm volatile("cp.async.wait_group 0;\n");   // own C[s+1] chunks landed
    }

    // ---- epilogue: v_126 in scr parity 1; dot with last-site vector ----
    __syncthreads();
    {
        const int par = (NSTEP - 1) & 1;   // = 1
        #pragma unroll
        for (int v = 0; v < 2; ++v) {
            int slot = lane + 32 * v;
            int pi = slot >> 4;
            int ro = slot & 15;
            float2 contrib = make_float2(0.f, 0.f);
            int valid = (pi < Pw);
            int pb = base + (valid ? pi : 0);
            if (valid) {
                int l = 16 * q + ro;
                const float2* sp = scrf + (size_t)((par * 4) * NPAIR + pb) * 64 + l;
                float2 a = sp[0];
                float2 b = sp[NPAIR * 64];
                float2 c = sp[2 * NPAIR * 64];
                float2 d = sp[3 * NPAIR * 64];
                float va = (a.x + b.x) + (c.x + d.x);
                float vv = (a.y + b.y) + (c.y + d.y);
                float4 l4  = *(const float4*)(lc + l * 4);
                float4 xe0 = *(const float4*)(x + xo0[pi] + 127 * 4);
                float4 xe1 = *(const float4*)(x + xo1[pi] + 127 * 4);
                float lva = l4.x*xe0.x + l4.y*xe0.y + l4.z*xe0.z + l4.w*xe0.w;
                float lvb = l4.x*xe1.x + l4.y*xe1.y + l4.z*xe1.z + l4.w*xe1.w;
                contrib = make_float2(va * lva, vv * lvb);
            }
            // reduce over ro within each 16-lane group
            #pragma unroll
            for (int off = 8; off > 0; off >>= 1) {
                contrib.x += __shfl_down_sync(0xffffffffu, contrib.x, off, 16);
                contrib.y += __shfl_down_sync(0xffffffffu, contrib.y, off, 16);
            }
            __syncwarp();                      // scr reads done before epi alias write
            if (ro == 0 && valid)
                epi[q * NPAIR + pb] = contrib; // parity-0 region, disjoint from par1
        }
    }
    __syncthreads();
    if (tid < TB) {
        int b = blockIdx.x * TB + tid;
        if (b < BATCH) {
            int pb = tid >> 1;
            float sum = 0.f;
            #pragma unroll
            for (int qq = 0; qq < 4; ++qq) {
                float2 e = epi[qq * NPAIR + pb];
                sum += (tid & 1) ? e.y : e.x;
            }
            out[b] = sum;
        }
    }
}

extern "C" void kernel_launch(void* const* d_in, const int* in_sizes, int n_in,
                              void* d_out, int out_size) {
    const float* x  = (const float*)d_in[0];   // input_data [4096,128,4]
    const float* fc = (const float*)d_in[1];   // first_core [4,64]
    const float* mc = (const float*)d_in[2];   // mid_cores  [126,64,4,64]
    const float* lc = (const float*)d_in[3];   // last_core  [64,4]
    float* out = (float*)d_out;

    cudaFuncSetAttribute(tt_chain_kernel,
                         cudaFuncAttributeMaxDynamicSharedMemorySize, SMEM_BYTES);

    tt_chain_kernel<<<GRID, THREADS, SMEM_BYTES>>>(x, fc, mc, lc, out);
}

// round 11
// speedup vs baseline: 1.0138x; 1.0138x over previous
#include <cuda_runtime.h>
#include <cstdint>

// Tensor-train chain, fp32 f32x2, TB=28/grid=147.
// R11: de-phased sg-groups with CLOSED ownership (fix of R10 race):
//   q  = warp&3  -> SMSP id (quarter of l)
//   sg = warp>>2 -> independent group; owns FIXED pair range for all quarters
// Non-rotated split {4,4,3,3} -> per-SMSP load is 4+4+3+3 = 14 pairs (balanced).
// C tile via TMA bulk + mbarrier full/empty pipeline; per-group named barriers.

#define BATCH   4096
#define LEN     128
#define RANK    64
#define NSTEP   126
#define CSTEP   16384          // floats per mid-core step (64 KB)
#define CBYTES  65536
#define TB      28             // batches per CTA (14 pairs)
#define NPAIR   14
#define GRID    147            // 147*28 = 4116 >= 4096
#define THREADS 512
#define VPITCH  66             // f32x2 per vbuf pair-row (64 + 2 pad)

// dynamic smem: Cbuf 2*CSTEP floats | vbuf [14][VPITCH] f32x2 | scr [2][4][14][32] ull2
#define SCR_U2  (2*4*NPAIR*32)
#define SMEM_BYTES (2*CSTEP*4 + NPAIR*VPITCH*8 + SCR_U2*16)

extern __shared__ float smem_f[];

__device__ __forceinline__ uint64_t fma2(uint64_t a, uint64_t b, uint64_t c) {
    uint64_t d;
    asm("fma.rn.f32x2 %0, %1, %2, %3;" : "=l"(d) : "l"(a), "l"(b), "l"(c));
    return d;
}
__device__ __forceinline__ uint64_t mul2(uint64_t a, uint64_t b) {
    uint64_t d;
    asm("mul.rn.f32x2 %0, %1, %2;" : "=l"(d) : "l"(a), "l"(b));
    return d;
}
__device__ __forceinline__ uint64_t dup2(float f) {
    uint64_t d;
    asm("mov.b64 %0, {%1, %1};" : "=l"(d) : "f"(f));
    return d;
}
__device__ __forceinline__ uint32_t smem_u32(const void* p) {
    return (uint32_t)__cvta_generic_to_shared(p);
}
__device__ __forceinline__ void mbar_init(uint32_t mbar, uint32_t cnt) {
    asm volatile("mbarrier.init.shared.b64 [%0], %1;" :: "r"(mbar), "r"(cnt) : "memory");
}
__device__ __forceinline__ void mbar_arrive(uint32_t mbar) {
    asm volatile("mbarrier.arrive.shared.b64 _, [%0];" :: "r"(mbar) : "memory");
}
__device__ __forceinline__ void mbar_expect_tx(uint32_t mbar, uint32_t tx) {
    asm volatile("mbarrier.arrive.expect_tx.shared.b64 _, [%0], %1;"
                 :: "r"(mbar), "r"(tx) : "memory");
}
__device__ __forceinline__ void mbar_wait(uint32_t mbar, uint32_t parity) {
    asm volatile(
        "{\n\t.reg .pred P;\n\t"
        "W%=:\n\t"
        "mbarrier.try_wait.parity.acquire.cta.shared::cta.b64 P, [%0], %1, 0x989680;\n\t"
        "@P bra D%=;\n\t"
        "bra W%=;\n\t"
        "D%=:\n\t}"
        :: "r"(mbar), "r"(parity) : "memory");
}
__device__ __forceinline__ void tma_bulk(uint32_t dst, const void* src,
                                         uint32_t bytes, uint32_t mbar) {
    asm volatile(
        "cp.async.bulk.shared::cta.global.mbarrier::complete_tx::bytes [%0], [%1], %2, [%3];"
        :: "r"(dst), "l"(src), "r"(bytes), "r"(mbar) : "memory");
}
__device__ __forceinline__ void gbar(int id) {
    asm volatile("bar.sync %0, %1;" :: "r"(id), "r"(128) : "memory");
}

// One step's heavy work for a warp owning P pairs (R8 math).
template<int P>
__device__ __forceinline__ void step_body(
    int s, const float2* __restrict__ CsL, const float2* __restrict__ vrow,
    const float* __restrict__ x, const int* xo0, const int* xo1,
    ulonglong2* __restrict__ scrW, int lane)
{
    uint64_t t[4][P][2];
    #pragma unroll
    for (int i = 0; i < 4; ++i)
        #pragma unroll
        for (int p = 0; p < P; ++p) { t[i][p][0] = 0ull; t[i][p][1] = 0ull; }

    #pragma unroll
    for (int h = 0; h < 8; ++h) {
        const int l2 = 2 * h;
        uint64_t vA[P], vB[P];
        #pragma unroll
        for (int p = 0; p < P; ++p) {
            ulonglong2 V = *(const ulonglong2*)(vrow + p * VPITCH + l2);
            vA[p] = V.x;
            vB[p] = V.y;
        }
        #pragma unroll
        for (int li = 0; li < 2; ++li) {
            #pragma unroll
            for (int i = 0; i < 4; ++i) {
                float2 c = CsL[(4 * (l2 + li) + i) * 32];
                uint64_t ca = dup2(c.x), cb = dup2(c.y);
                #pragma unroll
                for (int p = 0; p < P; ++p) {
                    uint64_t vv = li ? vB[p] : vA[p];
                    t[i][p][0] = fma2(vv, ca, t[i][p][0]);
                    t[i][p][1] = fma2(vv, cb, t[i][p][1]);
                }
            }
        }
    }

    #pragma unroll
    for (int p = 0; p < P; ++p) {
        float4 xa = *(const float4*)(x + xo0[p] + (s + 1) * 4);
        float4 xb = *(const float4*)(x + xo1[p] + (s + 1) * 4);
        uint64_t xp0 = ((uint64_t)__float_as_uint(xb.x) << 32) | __float_as_uint(xa.x);
        uint64_t xp1 = ((uint64_t)__float_as_uint(xb.y) << 32) | __float_as_uint(xa.y);
        uint64_t xp2 = ((uint64_t)__float_as_uint(xb.z) << 32) | __float_as_uint(xa.z);
        uint64_t xp3 = ((uint64_t)__float_as_uint(xb.w) << 32) | __float_as_uint(xa.w);
        uint64_t n0 = mul2(xp0, t[0][p][0]);
        n0 = fma2(xp1, t[1][p][0], n0);
        n0 = fma2(xp2, t[2][p][0], n0);
        n0 = fma2(xp3, t[3][p][0], n0);
        uint64_t n1 = mul2(xp0, t[0][p][1]);
        n1 = fma2(xp1, t[1][p][1], n1);
        n1 = fma2(xp2, t[2][p][1], n1);
        n1 = fma2(xp3, t[3][p][1], n1);
        ulonglong2 w; w.x = n0; w.y = n1;
        scrW[p * 32 + lane] = w;
    }
}

__global__ void __launch_bounds__(THREADS, 1)
tt_chain_kernel(const float* __restrict__ x,    // [B, 128, 4]
                const float* __restrict__ fc,   // [4, 64]
                const float* __restrict__ mc,   // [126, 64, 4, 64]
                const float* __restrict__ lc,   // [64, 4]
                float* __restrict__ out)        // [B, 1]
{
    float*      Cbuf = smem_f;
    float2*     vbuf = (float2*)(smem_f + 2*CSTEP);        // [14][VPITCH]
    ulonglong2* scr  = (ulonglong2*)(vbuf + NPAIR*VPITCH); // [2][4][14][32]
    float2*     scrf = (float2*)scr;                        // f2 view
    float2*     epi  = (float2*)scr;                        // parity-0 alias

    __shared__ __align__(8) uint64_t mbar_s[4];   // full0, full1, empty0, empty1
    uint32_t mb_full[2]  = { smem_u32(&mbar_s[0]), smem_u32(&mbar_s[1]) };
    uint32_t mb_empty[2] = { smem_u32(&mbar_s[2]), smem_u32(&mbar_s[3]) };

    const int tid  = threadIdx.x;
    const int warp = tid >> 5;
    const int lane = tid & 31;
    const int q    = warp & 3;             // l-quarter [16q,16q+16) AND SMSP id
    const int sg   = warp >> 2;            // independent group (fixed pair range)
    const int Pw   = (sg < 2) ? 4 : 3;
    const int base = (sg < 2) ? sg * 4 : 8 + (sg - 2) * 3;   // {0,4,8,11}

    int xo0[4], xo1[4];
    #pragma unroll
    for (int p = 0; p < 4; ++p) {
        int pb = base + p;
        int b0 = blockIdx.x * TB + 2 * pb;
        int b1 = b0 + 1;
        if (b0 > BATCH - 1) b0 = BATCH - 1;
        if (b1 > BATCH - 1) b1 = BATCH - 1;
        xo0[p] = b0 * (LEN * 4);
        xo1[p] = b1 * (LEN * 4);
    }

    // ---- mbarrier init + prologue TMA for C[0], C[1] ----
    if (tid == 0) {
        mbar_init(mb_full[0], 1);
        mbar_init(mb_full[1], 1);
        mbar_init(mb_empty[0], 16);
        mbar_init(mb_empty[1], 16);
    }
    __syncthreads();
    if (tid == 0) {
        #pragma unroll
        for (int b = 0; b < 2; ++b) {
            mbar_expect_tx(mb_full[b], CBYTES);
            uint32_t dst = smem_u32(Cbuf + b * CSTEP);
            const char* src = (const char*)(mc + (size_t)b * CSTEP);
            #pragma unroll
            for (int j = 0; j < 4; ++j)
                tma_bulk(dst + j * 16384, src + j * 16384, 16384, mb_full[b]);
        }
    }

    // ---- prologue: fill this warp's vbuf slots with v0 (warp-private) ----
    #pragma unroll
    for (int v = 0; v < 2; ++v) {
        int slot = lane + 32 * v;
        int pi = slot >> 4;
        int ro = slot & 15;
        if (pi < Pw) {
            int l = 16 * q + ro;
            float4 xA = *(const float4*)(x + xo0[pi]);
            float4 xB = *(const float4*)(x + xo1[pi]);
            float f0 = fc[l], f1 = fc[64 + l], f2 = fc[128 + l], f3 = fc[192 + l];
            float vx = f0*xA.x + f1*xA.y + f2*xA.z + f3*xA.w;
            float vy = f0*xB.x + f1*xB.y + f2*xB.z + f3*xB.w;
            vbuf[(base + pi) * VPITCH + l] = make_float2(vx, vy);
        }
    }

    int pf[2] = {0, 0};          // full-phase cursors (all warps)
    int pe[2] = {0, 0};          // empty-phase cursors (producer only)

    // ---- main chain: group-local barrier; C via mbarrier pipeline ----
    #pragma unroll 1
    for (int s = 0; s < NSTEP; ++s) {
        gbar(1 + sg);   // group sg: all 4 quarters finished step s-1

        // finalize v_s into vbuf (warp-private slots; partials all from THIS group)
        if (s > 0) {
            const int par = (s - 1) & 1;
            #pragma unroll
            for (int v = 0; v < 2; ++v) {
                int slot = lane + 32 * v;
                int pi = slot >> 4;
                int ro = slot & 15;
                if (pi < Pw) {
                    int pb = base + pi;
                    int l  = 16 * q + ro;
                    const float2* sp = scrf + (size_t)((par * 4) * NPAIR + pb) * 64 + l;
                    float2 a = sp[0];
                    float2 b = sp[NPAIR * 64];
                    float2 c = sp[2 * NPAIR * 64];
                    float2 d = sp[3 * NPAIR * 64];
                    vbuf[pb * VPITCH + l] =
                        make_float2((a.x + b.x) + (c.x + d.x),
                                    (a.y + b.y) + (c.y + d.y));
                }
            }
        }
        __syncwarp();

        // wait for C[s] (acquire)
        mbar_wait(mb_full[s & 1], pf[s & 1]);
        pf[s & 1] ^= 1;

        const float2* CsL = (const float2*)(Cbuf + (s & 1) * CSTEP)
                          + (size_t)(64 * q) * 32 + lane;
        const float2* vrow = vbuf + base * VPITCH + 16 * q;
        ulonglong2* scrW = scr + (size_t)(((s & 1) * 4 + q) * NPAIR + base) * 32;

        if (Pw == 4) step_body<4>(s, CsL, vrow, x, xo0, xo1, scrW, lane);
        else         step_body<3>(s, CsL, vrow, x, xo0, xo1, scrW, lane);

        __syncwarp();
        if (lane == 0) mbar_arrive(mb_empty[s & 1]);   // done reading C[s]

        // producer: refill buf[s&1] with C[s+2] once all 16 warps released it
        if (warp == 0 && lane == 0 && s + 2 < NSTEP) {
            mbar_wait(mb_empty[s & 1], pe[s & 1]);
            pe[s & 1] ^= 1;
            mbar_expect_tx(mb_full[s & 1], CBYTES);
            uint32_t dst = smem_u32(Cbuf + (s & 1) * CSTEP);
            const char* src = (const char*)(mc + (size_t)(s + 2) * CSTEP);
            #pragma unroll
            for (int j = 0; j < 4; ++j)
                tma_bulk(dst + j * 16384, src + j * 16384, 16384, mb_full[s & 1]);
        }
    }

    // ---- epilogue: v_126 in scr parity 1; dot with last-site vector ----
    __syncthreads();   // all groups past their loops; all scratch writes done
    {
        const int par = (NSTEP - 1) & 1;   // = 1
        #pragma unroll
        for (int v = 0; v < 2; ++v) {
            int slot = lane + 32 * v;
            int pi = slot >> 4;
            int ro = slot & 15;
            float2 contrib = make_float2(0.f, 0.f);
            int valid = (pi < Pw);
            int pb = base + (valid ? pi : 0);
            if (valid) {
                int l = 16 * q + ro;
                const float2* sp = scrf + (size_t)((par * 4) * NPAIR + pb) * 64 + l;
                float2 a = sp[0];
                float2 b = sp[NPAIR * 64];
                float2 c = sp[2 * NPAIR * 64];
                float2 d = sp[3 * NPAIR * 64];
                float vx = (a.x + b.x) + (c.x + d.x);
                float vy = (a.y + b.y) + (c.y + d.y);
                float4 l4  = *(const float4*)(lc + l * 4);
                float4 xe0 = *(const float4*)(x + xo0[pi] + 127 * 4);
                float4 xe1 = *(const float4*)(x + xo1[pi] + 127 * 4);
                float lva = l4.x*xe0.x + l4.y*xe0.y + l4.z*xe0.z + l4.w*xe0.w;
                float lvb = l4.x*xe1.x + l4.y*xe1.y + l4.z*xe1.z + l4.w*xe1.w;
                contrib = make_float2(vx * lva, vy * lvb);
            }
            #pragma unroll
            for (int off = 8; off > 0; off >>= 1) {
                contrib.x += __shfl_down_sync(0xffffffffu, contrib.x, off, 16);
                contrib.y += __shfl_down_sync(0xffffffffu, contrib.y, off, 16);
            }
            __syncwarp();                      // par-1 reads done before epi (par-0) write
            if (ro == 0 && valid)
                epi[q * NPAIR + pb] = contrib;
        }
    }
    __syncthreads();
    if (tid < TB) {
        int b = blockIdx.x * TB + tid;
        if (b < BATCH) {
            int pb = tid >> 1;
            float sum = 0.f;
            #pragma unroll
            for (int qq = 0; qq < 4; ++qq) {
                float2 e = epi[qq * NPAIR + pb];
                sum += (tid & 1) ? e.y : e.x;
            }
            out[b] = sum;
        }
    }
}

extern "C" void kernel_launch(void* const* d_in, const int* in_sizes, int n_in,
                              void* d_out, int out_size) {
    const float* x  = (const float*)d_in[0];   // input_data [4096,128,4]
    const float* fc = (const float*)d_in[1];   // first_core [4,64]
    const float* mc = (const float*)d_in[2];   // mid_cores  [126,64,4,64]
    const float* lc = (const float*)d_in[3];   // last_core  [64,4]
    float* out = (float*)d_out;

    cudaFuncSetAttribute(tt_chain_kernel,
                         cudaFuncAttributeMaxDynamicSharedMemorySize, SMEM_BYTES);

    tt_chain_kernel<<<GRID, THREADS, SMEM_BYTES>>>(x, fc, mc, lc, out);
}

// round 12
// speedup vs baseline: 1.0745x; 1.0598x over previous
#include <cuda_runtime.h>
#include <cstdint>

// Tensor-train chain, fp32 f32x2, TB=28/grid=147 (R8 base = best 385.5us).
// R12: per-step x vectors staged through a 2-slot smem ring via one 16B
// cp.async per batch per step (folded into the C commit group), so the
// combine stage reads x with broadcast LDS instead of exposed L2-latency
// LDG.128 at the step tail. Everything else identical to R8.

#define BATCH   4096
#define LEN     128
#define RANK    64
#define NSTEP   126
#define CSTEP   16384          // floats per mid-core step
#define TB      28             // batches per CTA (14 pairs)
#define NPAIR   14
#define GRID    147            // 147*28 = 4116 >= 4096
#define THREADS 512
#define VPITCH  66             // f32x2 per vbuf pair-row (64 + 2 pad)

// smem: Cbuf 2*CSTEP floats | vbuf [14][VPITCH] f32x2 | scr [2][4][14][32] ull2
//       | xring [2][TB][4] floats
#define SCR_U2  (2*4*NPAIR*32)
#define SMEM_BYTES (2*CSTEP*4 + NPAIR*VPITCH*8 + SCR_U2*16 + 2*TB*4*4)

extern __shared__ float smem_f[];

__device__ __forceinline__ uint64_t fma2(uint64_t a, uint64_t b, uint64_t c) {
    uint64_t d;
    asm("fma.rn.f32x2 %0, %1, %2, %3;" : "=l"(d) : "l"(a), "l"(b), "l"(c));
    return d;
}
__device__ __forceinline__ uint64_t mul2(uint64_t a, uint64_t b) {
    uint64_t d;
    asm("mul.rn.f32x2 %0, %1, %2;" : "=l"(d) : "l"(a), "l"(b));
    return d;
}
__device__ __forceinline__ uint64_t dup2(float f) {
    uint64_t d;
    asm("mov.b64 %0, {%1, %1};" : "=l"(d) : "f"(f));
    return d;
}
__device__ __forceinline__ uint64_t pack2(float a, float b) {
    uint64_t d;
    asm("mov.b64 %0, {%1, %2};" : "=l"(d) : "f"(a), "f"(b));
    return d;
}
__device__ __forceinline__ uint32_t smem_u32(const void* p) {
    return (uint32_t)__cvta_generic_to_shared(p);
}
__device__ __forceinline__ void cp_async16(uint32_t dst, const void* src) {
    asm volatile("cp.async.cg.shared.global [%0], [%1], 16;\n" :: "r"(dst), "l"(src));
}

// One step's heavy work for a warp owning P pairs (R8 math).
// CsL : float2 view of current C quarter, pre-offset by lane.
// vrow: vbuf rows for this warp's pairs ([p*VPITCH + llocal]).
// xrp : smem x for site s+1, pre-offset to this warp's first batch (floats).
// scrW: scratch write base (ull2) for (parity, q, base), [p*32 + lane].
template<int P>
__device__ __forceinline__ void step_body(
    const float2* __restrict__ CsL, const float2* __restrict__ vrow,
    const float* __restrict__ xrp,
    ulonglong2* __restrict__ scrW, int lane)
{
    uint64_t t[4][P][2];
    #pragma unroll
    for (int i = 0; i < 4; ++i)
        #pragma unroll
        for (int p = 0; p < P; ++p) { t[i][p][0] = 0ull; t[i][p][1] = 0ull; }

    #pragma unroll
    for (int h = 0; h < 8; ++h) {
        const int l2 = 2 * h;
        uint64_t vA[P], vB[P];
        #pragma unroll
        for (int p = 0; p < P; ++p) {
            ulonglong2 V = *(const ulonglong2*)(vrow + p * VPITCH + l2);
            vA[p] = V.x;                    // {v_a[l2],   v_b[l2]}
            vB[p] = V.y;                    // {v_a[l2+1], v_b[l2+1]}
        }
        #pragma unroll
        for (int li = 0; li < 2; ++li) {
            #pragma unroll
            for (int i = 0; i < 4; ++i) {
                float2 c = CsL[(4 * (l2 + li) + i) * 32];
                uint64_t ca = dup2(c.x), cb = dup2(c.y);
                #pragma unroll
                for (int p = 0; p < P; ++p) {
                    uint64_t vv = li ? vB[p] : vA[p];
                    t[i][p][0] = fma2(vv, ca, t[i][p][0]);   // batches, r0
                    t[i][p][1] = fma2(vv, cb, t[i][p][1]);   // batches, r1
                }
            }
        }
    }

    // combine with x[., s+1, .] (broadcast LDS from the ring) and write partials
    #pragma unroll
    for (int p = 0; p < P; ++p) {
        float4 xa = *(const float4*)(xrp + p * 8);       // batch 2*(base+p)
        float4 xb = *(const float4*)(xrp + p * 8 + 4);   // batch 2*(base+p)+1
        uint64_t xp0 = pack2(xa.x, xb.x);
        uint64_t xp1 = pack2(xa.y, xb.y);
        uint64_t xp2 = pack2(xa.z, xb.z);
        uint64_t xp3 = pack2(xa.w, xb.w);
        uint64_t n0 = mul2(xp0, t[0][p][0]);
        n0 = fma2(xp1, t[1][p][0], n0);
        n0 = fma2(xp2, t[2][p][0], n0);
        n0 = fma2(xp3, t[3][p][0], n0);
        uint64_t n1 = mul2(xp0, t[0][p][1]);
        n1 = fma2(xp1, t[1][p][1], n1);
        n1 = fma2(xp2, t[2][p][1], n1);
        n1 = fma2(xp3, t[3][p][1], n1);
        ulonglong2 w; w.x = n0; w.y = n1;    // {va_r0,vb_r0},{va_r1,vb_r1}
        scrW[p * 32 + lane] = w;
    }
}

__global__ void __launch_bounds__(THREADS, 1)
tt_chain_kernel(const float* __restrict__ x,    // [B, 128, 4]
                const float* __restrict__ fc,   // [4, 64]
                const float* __restrict__ mc,   // [126, 64, 4, 64]
                const float* __restrict__ lc,   // [64, 4]
                float* __restrict__ out)        // [B, 1]
{
    float*      Cbuf = smem_f;
    float2*     vbuf = (float2*)(smem_f + 2*CSTEP);        // [14][VPITCH]
    ulonglong2* scr  = (ulonglong2*)(vbuf + NPAIR*VPITCH); // [2][4][14][32]
    float2*     scrf = (float2*)scr;                        // f2 view
    float2*     epi  = (float2*)scr;                        // parity-0 alias
    float*      xs   = (float*)(scr + SCR_U2);              // [2][TB][4]

    const int tid  = threadIdx.x;
    const int warp = tid >> 5;
    const int lane = tid & 31;
    const int q    = warp >> 2;            // l-quarter [16q, 16q+16)
    const int sg   = warp & 3;             // -> SMSP
    const int Pw   = (((q + sg) & 3) < 2) ? 4 : 3;
    int base = 0;
    #pragma unroll
    for (int t = 0; t < 3; ++t)
        if (t < sg) base += (((q + t) & 3) < 2) ? 4 : 3;

    // ---- prefetch C[0]; stage x(site 1) into ring slot 1 ----
    {
        uint32_t dst = smem_u32(Cbuf);
        #pragma unroll
        for (int j = 0; j < 8; ++j) {
            int idx = j * THREADS + tid;           // 4096 16B chunks
            cp_async16(dst + idx * 16, mc + idx * 4);
        }
        if (tid < TB) {
            int gb = blockIdx.x * TB + tid;
            if (gb > BATCH - 1) gb = BATCH - 1;
            cp_async16(smem_u32(xs + (1 & 1) * (TB * 4) + tid * 4),
                       x + (size_t)gb * (LEN * 4) + 1 * 4);
        }
        asm volatile("cp.async.commit_group;\n");
    }

    // ---- prologue: fill this warp's vbuf slots with v0 (gmem x, one-time) ----
    #pragma unroll
    for (int v = 0; v < 2; ++v) {
        int slot = lane + 32 * v;
        int pi = slot >> 4;
        int ro = slot & 15;
        if (pi < Pw) {
            int l = 16 * q + ro;
            int b0 = blockIdx.x * TB + 2 * (base + pi);
            int b1 = b0 + 1;
            if (b0 > BATCH - 1) b0 = BATCH - 1;
            if (b1 > BATCH - 1) b1 = BATCH - 1;
            float4 xA = *(const float4*)(x + (size_t)b0 * (LEN * 4));
            float4 xB = *(const float4*)(x + (size_t)b1 * (LEN * 4));
            float f0 = fc[l], f1 = fc[64 + l], f2 = fc[128 + l], f3 = fc[192 + l];
            float vx = f0*xA.x + f1*xA.y + f2*xA.z + f3*xA.w;
            float vy = f0*xB.x + f1*xB.y + f2*xB.z + f3*xB.w;
            vbuf[(base + pi) * VPITCH + l] = make_float2(vx, vy);
        }
    }
    asm volatile("cp.async.wait_group 0;\n");   // own C[0] + x(1) chunks landed

    // ---- main chain: ONE __syncthreads per step ----
    #pragma unroll 1
    for (int s = 0; s < NSTEP; ++s) {
        __syncthreads();   // C[s], x(s+1) visible; scr[(s-1)&1] complete; buffers free

        // prefetch C[s+1] and x(s+2) (same commit group)
        if (s + 1 < NSTEP) {
            uint32_t dst = smem_u32(Cbuf + ((s + 1) & 1) * CSTEP);
            const float* src = mc + (size_t)(s + 1) * CSTEP;
            #pragma unroll
            for (int j = 0; j < 8; ++j) {
                int idx = j * THREADS + tid;
                cp_async16(dst + idx * 16, src + idx * 4);
            }
        }
        if (s + 2 <= LEN - 1 && tid < TB) {
            int gb = blockIdx.x * TB + tid;
            if (gb > BATCH - 1) gb = BATCH - 1;
            cp_async16(smem_u32(xs + ((s + 2) & 1) * (TB * 4) + tid * 4),
                       x + (size_t)gb * (LEN * 4) + (size_t)(s + 2) * 4);
        }
        asm volatile("cp.async.commit_group;\n");

        // finalize v_s into vbuf (warp-private slots), except s==0
        if (s > 0) {
            const int par = (s - 1) & 1;
            #pragma unroll
            for (int v = 0; v < 2; ++v) {
                int slot = lane + 32 * v;
                int pi = slot >> 4;
                int ro = slot & 15;
                if (pi < Pw) {
                    int pb = base + pi;
                    int l  = 16 * q + ro;
                    const float2* sp = scrf + (size_t)((par * 4) * NPAIR + pb) * 64 + l;
                    float2 a = sp[0];
                    float2 b = sp[NPAIR * 64];
                    float2 c = sp[2 * NPAIR * 64];
                    float2 d = sp[3 * NPAIR * 64];
                    vbuf[pb * VPITCH + l] =
                        make_float2((a.x + b.x) + (c.x + d.x),
                                    (a.y + b.y) + (c.y + d.y));
                }
            }
        }
        __syncwarp();

        const float2* CsL = (const float2*)(Cbuf + (s & 1) * CSTEP)
                          + (size_t)(64 * q) * 32 + lane;
        const float2* vrow = vbuf + base * VPITCH + 16 * q;
        const float* xrp = xs + ((s + 1) & 1) * (TB * 4) + base * 8;
        ulonglong2* scrW = scr + (size_t)(((s & 1) * 4 + q) * NPAIR + base) * 32;

        if (Pw == 4) step_body<4>(CsL, vrow, xrp, scrW, lane);
        else         step_body<3>(CsL, vrow, xrp, scrW, lane);

        asm volatile("cp.async.wait_group 0;\n");   // own C[s+1] + x(s+2) landed
    }

    // ---- epilogue: v_126 in scr parity 1; dot with last-site vector ----
    __syncthreads();   // all scratch writes + x(127) staging visible
    {
        const int par = (NSTEP - 1) & 1;   // = 1
        const float* xr127 = xs + ((LEN - 1) & 1) * (TB * 4);
        #pragma unroll
        for (int v = 0; v < 2; ++v) {
            int slot = lane + 32 * v;
            int pi = slot >> 4;
            int ro = slot & 15;
            float2 contrib = make_float2(0.f, 0.f);
            int valid = (pi < Pw);
            int pb = base + (valid ? pi : 0);
            if (valid) {
                int l = 16 * q + ro;
                const float2* sp = scrf + (size_t)((par * 4) * NPAIR + pb) * 64 + l;
                float2 a = sp[0];
                float2 b = sp[NPAIR * 64];
                float2 c = sp[2 * NPAIR * 64];
                float2 d = sp[3 * NPAIR * 64];
                float vx = (a.x + b.x) + (c.x + d.x);
                float vy = (a.y + b.y) + (c.y + d.y);
                float4 l4  = *(const float4*)(lc + l * 4);
                float4 xe0 = *(const float4*)(xr127 + (2 * pb) * 4);
                float4 xe1 = *(const float4*)(xr127 + (2 * pb + 1) * 4);
                float lva = l4.x*xe0.x + l4.y*xe0.y + l4.z*xe0.z + l4.w*xe0.w;
                float lvb = l4.x*xe1.x + l4.y*xe1.y + l4.z*xe1.z + l4.w*xe1.w;
                contrib = make_float2(vx * lva, vy * lvb);
            }
            #pragma unroll
            for (int off = 8; off > 0; off >>= 1) {
                contrib.x += __shfl_down_sync(0xffffffffu, contrib.x, off, 16);
                contrib.y += __shfl_down_sync(0xffffffffu, contrib.y, off, 16);
            }
            __syncwarp();                      // par-1 reads done before epi (par-0) write
            if (ro == 0 && valid)
                epi[q * NPAIR + pb] = contrib;
        }
    }
    __syncthreads();
    if (tid < TB) {
        int b = blockIdx.x * TB + tid;
        if (b < BATCH) {
            int pb = tid >> 1;
            float sum = 0.f;
            #pragma unroll
            for (int qq = 0; qq < 4; ++qq) {
                float2 e = epi[qq * NPAIR + pb];
                sum += (tid & 1) ? e.y : e.x;
            }
            out[b] = sum;
        }
    }
}

extern "C" void kernel_launch(void* const* d_in, const int* in_sizes, int n_in,
                              void* d_out, int out_size) {
    const float* x  = (const float*)d_in[0];   // input_data [4096,128,4]
    const float* fc = (const float*)d_in[1];   // first_core [4,64]
    const float* mc = (const float*)d_in[2];   // mid_cores  [126,64,4,64]
    const float* lc = (const float*)d_in[3];   // last_core  [64,4]
    float* out = (float*)d_out;

    cudaFuncSetAttribute(tt_chain_kernel,
                         cudaFuncAttributeMaxDynamicSharedMemorySize, SMEM_BYTES);

    tt_chain_kernel<<<GRID, THREADS, SMEM_BYTES>>>(x, fc, mc, lc, out);
}